// round 1
// baseline (speedup 1.0000x reference)
#include <cuda_runtime.h>

#define C_IN  64
#define C_OUT 32
#define WARPS_PER_BLOCK 8
#define MSGS_PER_WARP   32
#define THREADS (WARPS_PER_BLOCK * 32)

// Runtime-detected index width (reference's int64 maps may have been silently
// downcast to int32 by JAX when x64 is disabled). 1 => int64, 0 => int32.
__device__ int g_idx_is64;

__global__ void detect_idx_kernel(const long long* __restrict__ im) {
    // Reads 16 int64 = 128 bytes; even if the buffer is int32 it holds
    // K*M*4 >= 10 MB, so this never goes out of bounds.
    int is64 = 1;
#pragma unroll
    for (int t = 0; t < 16; ++t) {
        long long v = im[t];
        if (v < 0 || v >= (1ll << 31)) is64 = 0;
    }
    g_idx_is64 = is64;
}

template <typename IdxT>
__device__ __forceinline__ void warp_work(
    const float* __restrict__ feats, const float* __restrict__ Wk,
    const IdxT* __restrict__ in_map, const IdxT* __restrict__ out_map,
    float* __restrict__ out, long long base, int m0, int M, int lane)
{
    // Register-resident weight column: w[i] = W[k][i][lane]
    float w[C_IN];
#pragma unroll
    for (int i = 0; i < C_IN; ++i) w[i] = Wk[i * C_OUT + lane];

    const float2* feats2 = reinterpret_cast<const float2*>(feats);
    int mEnd = min(m0 + MSGS_PER_WARP, M);
    for (int m = m0; m < mEnd; ++m) {
        long long in_idx  = (long long)in_map[base + m];
        long long out_idx = (long long)out_map[base + m];
        // Coalesced 256B gather of the feats row: lane holds f[2*lane], f[2*lane+1]
        float2 f = feats2[in_idx * (C_IN / 2) + lane];
        float acc = 0.f;
#pragma unroll
        for (int j = 0; j < 32; ++j) {
            float fx = __shfl_sync(0xffffffffu, f.x, j);
            float fy = __shfl_sync(0xffffffffu, f.y, j);
            acc = fmaf(fx, w[2 * j],     acc);
            acc = fmaf(fy, w[2 * j + 1], acc);
        }
        atomicAdd(out + out_idx * C_OUT + lane, acc);
    }
}

__global__ void __launch_bounds__(THREADS)
spconv_kernel(const float* __restrict__ feats,
              const float* __restrict__ weight,
              const void*  __restrict__ in_map,
              const void*  __restrict__ out_map,
              float* __restrict__ out, int M)
{
    int k    = blockIdx.y;
    int wi   = threadIdx.x >> 5;
    int lane = threadIdx.x & 31;
    int m0 = (blockIdx.x * WARPS_PER_BLOCK + wi) * MSGS_PER_WARP;
    if (m0 >= M) return;

    const float* Wk = weight + (size_t)k * C_IN * C_OUT;
    long long base = (long long)k * M;

    if (g_idx_is64)
        warp_work<long long>(feats, Wk,
                             (const long long*)in_map, (const long long*)out_map,
                             out, base, m0, M, lane);
    else
        warp_work<int>(feats, Wk,
                       (const int*)in_map, (const int*)out_map,
                       out, base, m0, M, lane);
}

extern "C" void kernel_launch(void* const* d_in, const int* in_sizes, int n_in,
                              void* d_out, int out_size) {
    const float* feats  = (const float*)d_in[0];
    const float* weight = (const float*)d_in[1];
    const void*  in_map  = d_in[2];
    const void*  out_map = d_in[3];

    int K = in_sizes[1] / (C_IN * C_OUT);   // 27
    int M = in_sizes[2] / K;                // 100000

    // Output is poisoned before timing; scatter-add needs zeros.
    cudaMemsetAsync(d_out, 0, (size_t)out_size * sizeof(float));

    detect_idx_kernel<<<1, 1>>>((const long long*)in_map);

    dim3 grid((M + WARPS_PER_BLOCK * MSGS_PER_WARP - 1) /
                  (WARPS_PER_BLOCK * MSGS_PER_WARP),
              K);
    spconv_kernel<<<grid, THREADS>>>(feats, weight, in_map, out_map,
                                     (float*)d_out, M);
}

// round 3
// speedup vs baseline: 1.8200x; 1.8200x over previous
#include <cuda_runtime.h>

#define C_IN  64
#define C_OUT 32
#define WARPS_PER_BLOCK 8
#define MSGS_PER_WARP   16
#define THREADS (WARPS_PER_BLOCK * 32)

// Runtime-detected index width (reference's int64 maps may have been silently
// downcast to int32 by JAX when x64 is disabled). 1 => int64, 0 => int32.
__device__ int g_idx_is64;

__global__ void detect_idx_kernel(const long long* __restrict__ im) {
    int is64 = 1;
#pragma unroll
    for (int t = 0; t < 16; ++t) {
        long long v = im[t];
        if (v < 0 || v >= (1ll << 31)) is64 = 0;
    }
    g_idx_is64 = is64;
}

__device__ __forceinline__ unsigned long long pack2(float a, float b) {
    unsigned long long r;
    asm("mov.b64 %0, {%1, %2};" : "=l"(r) : "r"(__float_as_uint(a)), "r"(__float_as_uint(b)));
    return r;
}

template <typename IdxT>
__device__ __forceinline__ void warp_work(
    const float* __restrict__ feats, const float* __restrict__ Wk,
    const IdxT* __restrict__ in_map, const IdxT* __restrict__ out_map,
    float* __restrict__ out, float* __restrict__ tile,
    long long base, int m0, int M, int lane)
{
    // Pack this lane's weight column into 32 x f32x2 registers:
    // w2[j] = (Wk[2j][lane], Wk[2j+1][lane])
    unsigned long long w2[C_IN / 2];
#pragma unroll
    for (int j = 0; j < C_IN / 2; ++j) {
        float a = Wk[(2 * j)     * C_OUT + lane];
        float b = Wk[(2 * j + 1) * C_OUT + lane];
        w2[j] = pack2(a, b);
    }

    // Stage MSGS_PER_WARP feats rows into this warp's smem slice.
    // Two half-warps each load one row per iteration (16B per lane).
    const float4* feats4 = reinterpret_cast<const float4*>(feats);
    int half = lane >> 4;
    int elem = lane & 15;
    int mEnd = min(m0 + MSGS_PER_WARP, M);
#pragma unroll
    for (int r2 = 0; r2 < MSGS_PER_WARP; r2 += 2) {
        int r = r2 + half;
        int m = m0 + r;
        if (m < M) {
            long long in_idx = (long long)in_map[base + m];
            float4 v = feats4[in_idx * (C_IN / 4) + elem];
            *reinterpret_cast<float4*>(tile + r * C_IN + elem * 4) = v;
        }
    }
    __syncwarp();

    for (int m = m0; m < mEnd; ++m) {
        // Each ulonglong2 = 16 bytes = 4 floats; need C_IN/4 = 16 of them.
        const ulonglong2* frow =
            reinterpret_cast<const ulonglong2*>(tile + (m - m0) * C_IN);
        unsigned long long acc0 = 0ull, acc1 = 0ull;  // (0.f, 0.f)
#pragma unroll
        for (int jj = 0; jj < C_IN / 4; ++jj) {       // 16 x LDS.128 broadcast
            ulonglong2 v = frow[jj];                  // f[4jj .. 4jj+3]
            asm("fma.rn.f32x2 %0, %1, %2, %0;"
                : "+l"(acc0) : "l"(v.x), "l"(w2[2 * jj]));
            asm("fma.rn.f32x2 %0, %1, %2, %0;"
                : "+l"(acc1) : "l"(v.y), "l"(w2[2 * jj + 1]));
        }
        unsigned int l0, h0, l1, h1;
        asm("mov.b64 {%0, %1}, %2;" : "=r"(l0), "=r"(h0) : "l"(acc0));
        asm("mov.b64 {%0, %1}, %2;" : "=r"(l1), "=r"(h1) : "l"(acc1));
        float acc = (__uint_as_float(l0) + __uint_as_float(h0)) +
                    (__uint_as_float(l1) + __uint_as_float(h1));
        long long out_idx = (long long)out_map[base + m];
        atomicAdd(out + out_idx * C_OUT + lane, acc);
    }
}

__global__ void __launch_bounds__(THREADS)
spconv_kernel(const float* __restrict__ feats,
              const float* __restrict__ weight,
              const void*  __restrict__ in_map,
              const void*  __restrict__ out_map,
              float* __restrict__ out, int M)
{
    __shared__ float tile[WARPS_PER_BLOCK][MSGS_PER_WARP * C_IN];  // 32 KB

    int k    = blockIdx.y;
    int wi   = threadIdx.x >> 5;
    int lane = threadIdx.x & 31;
    int m0 = (blockIdx.x * WARPS_PER_BLOCK + wi) * MSGS_PER_WARP;
    if (m0 >= M) return;

    const float* Wk = weight + (size_t)k * C_IN * C_OUT;
    long long base = (long long)k * M;

    if (g_idx_is64)
        warp_work<long long>(feats, Wk,
                             (const long long*)in_map, (const long long*)out_map,
                             out, tile[wi], base, m0, M, lane);
    else
        warp_work<int>(feats, Wk,
                       (const int*)in_map, (const int*)out_map,
                       out, tile[wi], base, m0, M, lane);
}

extern "C" void kernel_launch(void* const* d_in, const int* in_sizes, int n_in,
                              void* d_out, int out_size) {
    const float* feats  = (const float*)d_in[0];
    const float* weight = (const float*)d_in[1];
    const void*  in_map  = d_in[2];
    const void*  out_map = d_in[3];

    int K = in_sizes[1] / (C_IN * C_OUT);   // 27
    int M = in_sizes[2] / K;                // 100000

    cudaMemsetAsync(d_out, 0, (size_t)out_size * sizeof(float));
    detect_idx_kernel<<<1, 1>>>((const long long*)in_map);

    dim3 grid((M + WARPS_PER_BLOCK * MSGS_PER_WARP - 1) /
                  (WARPS_PER_BLOCK * MSGS_PER_WARP),
              K);
    spconv_kernel<<<grid, THREADS>>>(feats, weight, in_map, out_map,
                                     (float*)d_out, M);
}

// round 5
// speedup vs baseline: 3.9139x; 2.1505x over previous
#include <cuda_runtime.h>
#include <cstdint>

#define C_IN    64
#define C_OUT   32
#define M_TILE  128
#define THREADS 128
#define GRID    608
#define A_STRIDE 68   // floats per row (64 + 4 pad): conflict-free frag loads

// Runtime-detected index width (reference's int64 maps may have been silently
// downcast to int32 by JAX when x64 is disabled).
__device__ int g_idx_is64;
__global__ void detect_idx_kernel(const long long* __restrict__ im) {
    int is64 = 1;
#pragma unroll
    for (int t = 0; t < 16; ++t) {
        long long v = im[t];
        if (v < 0 || v >= (1ll << 31)) is64 = 0;
    }
    g_idx_is64 = is64;
}

static __device__ __forceinline__ uint32_t cvt_tf32(float f) {
    uint32_t r;
    asm("cvt.rna.tf32.f32 %0, %1;" : "=r"(r) : "f"(f));
    return r;
}

static __device__ __forceinline__ void mma_tf32(
    float& c0, float& c1, float& c2, float& c3,
    uint32_t a0, uint32_t a1, uint32_t a2, uint32_t a3,
    uint32_t b0, uint32_t b1)
{
    asm volatile(
        "mma.sync.aligned.m16n8k8.row.col.f32.tf32.tf32.f32 "
        "{%0,%1,%2,%3}, {%4,%5,%6,%7}, {%8,%9}, {%0,%1,%2,%3};"
        : "+f"(c0), "+f"(c1), "+f"(c2), "+f"(c3)
        : "r"(a0), "r"(a1), "r"(a2), "r"(a3), "r"(b0), "r"(b1));
}

static __device__ __forceinline__ void red_v2(float* p, float x, float y) {
    asm volatile("red.global.add.v2.f32 [%0], {%1, %2};"
                 :: "l"(p), "f"(x), "f"(y) : "memory");
}

struct SmemT {
    long long in_s[M_TILE];
    long long out_s[M_TILE];
    __align__(16) float A[M_TILE * A_STRIDE];   // raw f32 feats rows
};

__global__ void __launch_bounds__(THREADS, 4)
spconv_mma(const float* __restrict__ feats, const float* __restrict__ weight,
           const void* __restrict__ in_map, const void* __restrict__ out_map,
           float* __restrict__ out, int M, int tilesPerK, int nTiles, int chunk)
{
    __shared__ SmemT sm;
    const int tid  = threadIdx.x;
    const int wid  = tid >> 5;
    const int lane = tid & 31;
    const int grp  = lane >> 2;      // 0..7
    const int tig  = lane & 3;       // 0..3
    const int wbase = wid * 32;      // warp's 32 rows within the tile
    const int is64 = g_idx_is64;
    const float4* f4 = (const float4*)feats;

    const int t0 = blockIdx.x * chunk;
    const int tEnd = min(t0 + chunk, nTiles);
    if (t0 >= nTiles) return;

    uint32_t B[8][4][2];     // B-frags: [k-tile][n-tile][2], tf32
    int k_cur = -1;

    for (int t = t0; t < tEnd; ++t) {
        const int k  = t / tilesPerK;
        const int m0 = (t - k * tilesPerK) * M_TILE;
        const int rows = min(M_TILE, M - m0);

        __syncthreads();   // previous tile fully consumed before overwrite

        if (tid < rows) {
            long long base = (long long)k * M + m0 + tid;
            if (is64) {
                sm.in_s[tid]  = ((const long long*)in_map)[base];
                sm.out_s[tid] = ((const long long*)out_map)[base];
            } else {
                sm.in_s[tid]  = ((const int*)in_map)[base];
                sm.out_s[tid] = ((const int*)out_map)[base];
            }
        }

        if (k != k_cur) {   // weights -> register B-frags (rare: <=2x per CTA)
            k_cur = k;
            const float* Wk = weight + (size_t)k * C_IN * C_OUT;
#pragma unroll
            for (int kt = 0; kt < 8; ++kt)
#pragma unroll
                for (int nt = 0; nt < 4; ++nt) {
                    B[kt][nt][0] = cvt_tf32(Wk[(8 * kt + tig)     * C_OUT + 8 * nt + grp]);
                    B[kt][nt][1] = cvt_tf32(Wk[(8 * kt + tig + 4) * C_OUT + 8 * nt + grp]);
                }
        }
        __syncthreads();   // indices visible

        // gather 128 feats rows (raw f32) into padded smem
        {
            const int e = tid & 15, rg = tid >> 4;
#pragma unroll
            for (int p = 0; p < 16; ++p) {
                int r = p * 8 + rg;
                if (r < rows) {
                    long long ii = sm.in_s[r];
                    *(float4*)&sm.A[r * A_STRIDE + e * 4] = f4[ii * (C_IN / 4) + e];
                }
            }
        }
        __syncthreads();   // A visible

        // GEMM: 32 rows x 32 cols x 64 k per warp = 64 HMMA
        float acc[2][4][4];
#pragma unroll
        for (int mt = 0; mt < 2; ++mt)
#pragma unroll
            for (int nt = 0; nt < 4; ++nt)
#pragma unroll
                for (int i = 0; i < 4; ++i) acc[mt][nt][i] = 0.f;

#pragma unroll
        for (int kt = 0; kt < 8; ++kt) {
#pragma unroll
            for (int mt = 0; mt < 2; ++mt) {
                const float* Ar = &sm.A[(wbase + mt * 16 + grp) * A_STRIDE + kt * 8 + tig];
                uint32_t a0 = __float_as_uint(Ar[0]);
                uint32_t a1 = __float_as_uint(Ar[8 * A_STRIDE]);
                uint32_t a2 = __float_as_uint(Ar[4]);
                uint32_t a3 = __float_as_uint(Ar[8 * A_STRIDE + 4]);
#pragma unroll
                for (int nt = 0; nt < 4; ++nt)
                    mma_tf32(acc[mt][nt][0], acc[mt][nt][1], acc[mt][nt][2], acc[mt][nt][3],
                             a0, a1, a2, a3, B[kt][nt][0], B[kt][nt][1]);
            }
        }

        // epilogue: vector reductions straight from C-frags
#pragma unroll
        for (int mt = 0; mt < 2; ++mt) {
            int r0 = wbase + mt * 16 + grp;
            int r1 = r0 + 8;
            bool v0 = r0 < rows, v1 = r1 < rows;
            float* p0 = v0 ? out + (long long)sm.out_s[r0] * C_OUT + 2 * tig : nullptr;
            float* p1 = v1 ? out + (long long)sm.out_s[r1] * C_OUT + 2 * tig : nullptr;
#pragma unroll
            for (int nt = 0; nt < 4; ++nt) {
                if (v0) red_v2(p0 + 8 * nt, acc[mt][nt][0], acc[mt][nt][1]);
                if (v1) red_v2(p1 + 8 * nt, acc[mt][nt][2], acc[mt][nt][3]);
            }
        }
    }
}

extern "C" void kernel_launch(void* const* d_in, const int* in_sizes, int n_in,
                              void* d_out, int out_size) {
    const float* feats  = (const float*)d_in[0];
    const float* weight = (const float*)d_in[1];
    const void*  in_map  = d_in[2];
    const void*  out_map = d_in[3];

    int K = in_sizes[1] / (C_IN * C_OUT);           // 27
    int M = in_sizes[2] / K;                        // 100000
    int tilesPerK = (M + M_TILE - 1) / M_TILE;      // 782
    int nTiles = K * tilesPerK;                     // 21114
    int chunk = (nTiles + GRID - 1) / GRID;         // contiguous k-major chunks

    cudaMemsetAsync(d_out, 0, (size_t)out_size * sizeof(float));
    detect_idx_kernel<<<1, 1>>>((const long long*)in_map);
    spconv_mma<<<GRID, THREADS>>>(feats, weight, in_map, out_map,
                                  (float*)d_out, M, tilesPerK, nTiles, chunk);
}

// round 6
// speedup vs baseline: 5.1678x; 1.3204x over previous
#include <cuda_runtime.h>
#include <cstdint>

#define C_IN    64
#define C_OUT   32
#define M_TILE  128
#define THREADS 128
#define GRID    444
#define A_STRIDE_F  68                 // floats per A row (64 + 4 pad, conflict-free)
#define A_ROW_BYTES (A_STRIDE_F * 4)   // 272

// dynamic smem layout (byte offsets, all 16B aligned)
#define OFF_IN(s)   ((s) * 1024)            // 2 x 128 x int64 (or int32)
#define OFF_OUT(s)  (2048 + (s) * 1024)
#define OFF_MBAR    4096                    // 2 mbarriers
#define OFF_A(s)    (4352 + (s) * 34816)    // 2 x 128 x 272B
#define SMEM_TOTAL  (4352 + 2 * 34816)      // 73984

// Runtime-detected index width (reference's int64 maps may have been silently
// downcast to int32 by JAX when x64 is disabled).
__device__ int g_idx_is64;
__global__ void detect_idx_kernel(const long long* __restrict__ im) {
    int is64 = 1;
#pragma unroll
    for (int t = 0; t < 16; ++t) {
        long long v = im[t];
        if (v < 0 || v >= (1ll << 31)) is64 = 0;
    }
    g_idx_is64 = is64;
}

static __device__ __forceinline__ uint32_t smem_u32(const void* p) {
    uint32_t a;
    asm("{ .reg .u64 t; cvta.to.shared.u64 t, %1; cvt.u32.u64 %0, t; }" : "=r"(a) : "l"(p));
    return a;
}
static __device__ __forceinline__ uint32_t cvt_tf32(float f) {
    uint32_t r;
    asm("cvt.rna.tf32.f32 %0, %1;" : "=r"(r) : "f"(f));
    return r;
}
static __device__ __forceinline__ void mma_tf32(
    float& c0, float& c1, float& c2, float& c3,
    uint32_t a0, uint32_t a1, uint32_t a2, uint32_t a3,
    uint32_t b0, uint32_t b1)
{
    asm volatile(
        "mma.sync.aligned.m16n8k8.row.col.f32.tf32.tf32.f32 "
        "{%0,%1,%2,%3}, {%4,%5,%6,%7}, {%8,%9}, {%0,%1,%2,%3};"
        : "+f"(c0), "+f"(c1), "+f"(c2), "+f"(c3)
        : "r"(a0), "r"(a1), "r"(a2), "r"(a3), "r"(b0), "r"(b1));
}
static __device__ __forceinline__ void red_v2(float* p, float x, float y) {
    asm volatile("red.global.add.v2.f32 [%0], {%1, %2};"
                 :: "l"(p), "f"(x), "f"(y) : "memory");
}
static __device__ __forceinline__ void mbar_init(uint32_t a, uint32_t n) {
    asm volatile("mbarrier.init.shared.b64 [%0], %1;" :: "r"(a), "r"(n) : "memory");
}
static __device__ __forceinline__ void expect_tx(uint32_t a, uint32_t bytes) {
    asm volatile("mbarrier.arrive.expect_tx.shared.b64 _, [%0], %1;"
                 :: "r"(a), "r"(bytes) : "memory");
}
static __device__ __forceinline__ void mbar_wait(uint32_t a, uint32_t ph) {
    asm volatile("{\n\t.reg .pred P1;\n\t"
        "WL_%=:\n\t"
        "mbarrier.try_wait.parity.acquire.cta.shared::cta.b64 P1, [%0], %1, 0x989680;\n\t"
        "@P1 bra.uni WD_%=;\n\t"
        "bra.uni WL_%=;\n\t"
        "WD_%=:\n\t}" :: "r"(a), "r"(ph) : "memory");
}
static __device__ __forceinline__ void bulk_g2s(uint32_t dst, const void* src,
                                                uint32_t bytes, uint32_t mbar) {
    asm volatile(
        "cp.async.bulk.shared::cta.global.mbarrier::complete_tx::bytes [%0], [%1], %2, [%3];"
        :: "r"(dst), "l"(src), "r"(bytes), "r"(mbar) : "memory");
}
#define FENCE_ASYNC() asm volatile("fence.proxy.async.shared::cta;" ::: "memory")

__global__ void __launch_bounds__(THREADS, 3)
spconv_mma(const float* __restrict__ feats, const float* __restrict__ weight,
           const void* __restrict__ in_map, const void* __restrict__ out_map,
           float* __restrict__ out, int M, int tilesPerK, int nTiles, int chunk)
{
    extern __shared__ __align__(16) char smem[];
    const uint32_t sb = smem_u32(smem);

    const int t0 = blockIdx.x * chunk;
    if (t0 >= nTiles) return;
    const int tEnd = min(t0 + chunk, nTiles);

    const int tid  = threadIdx.x;
    const int wid  = tid >> 5;
    const int lane = tid & 31;
    const int grp  = lane >> 2;
    const int tig  = lane & 3;
    const int wbase = wid * 32;
    const int is64  = g_idx_is64;
    const int idxsz = is64 ? 8 : 4;

    if (tid == 0) { mbar_init(sb + OFF_MBAR, 1); mbar_init(sb + OFF_MBAR + 8, 1); }
    __syncthreads();

#define MBAR(s) (sb + OFF_MBAR + 8u * (uint32_t)(s))
#define ROWS_OF(t)   min(M_TILE, M - ((t) % tilesPerK) * M_TILE)
#define MAP_OFF(t)   ((long long)((t) / tilesPerK) * M + ((t) % tilesPerK) * M_TILE)

    int ph[2] = {0, 0};
    const int cur0 = t0 & 1, nxt0 = cur0 ^ 1;
    const int rows0 = ROWS_OF(t0);

    // ---- prologue stage A: fetch in-idx(t0) ----
    if (tid == 0) {
        expect_tx(MBAR(cur0), (uint32_t)(rows0 * idxsz));
        bulk_g2s(sb + OFF_IN(cur0), (const char*)in_map + MAP_OFF(t0) * idxsz,
                 rows0 * idxsz, MBAR(cur0));
    }
    mbar_wait(MBAR(cur0), 0); ph[cur0] = 1;

    // ---- prologue stage B: gather A(t0), out-idx(t0), in-idx(t0+1) ----
    {
        int rows1b = (t0 + 1 < tEnd) ? ROWS_OF(t0 + 1) : 0;
        uint32_t bytes = (uint32_t)(rows0 * 256 + rows0 * idxsz + rows1b * idxsz);
        if (tid == 0) expect_tx(MBAR(nxt0), bytes);
        if (tid < rows0) {
            long long ii = is64 ? ((const long long*)(smem + OFF_IN(cur0)))[tid]
                                : (long long)((const int*)(smem + OFF_IN(cur0)))[tid];
            bulk_g2s(sb + OFF_A(cur0) + tid * A_ROW_BYTES, feats + ii * C_IN, 256, MBAR(nxt0));
        }
        if (tid == 0)
            bulk_g2s(sb + OFF_OUT(cur0), (const char*)out_map + MAP_OFF(t0) * idxsz,
                     rows0 * idxsz, MBAR(nxt0));
        if (tid == 1 && rows1b)
            bulk_g2s(sb + OFF_IN(nxt0), (const char*)in_map + MAP_OFF(t0 + 1) * idxsz,
                     rows1b * idxsz, MBAR(nxt0));
    }

    uint32_t B[8][4][2];
    int k_cur = -1;

    for (int t = t0; t < tEnd; ++t) {
        const int cur = t & 1, nxt = cur ^ 1;

        // wait for everything issued last iteration (A[cur], idx for t+1, out-idx t)
        mbar_wait(MBAR(nxt), ph[nxt]); ph[nxt] ^= 1;
        __syncthreads();

        const int k    = t / tilesPerK;
        const int rows = ROWS_OF(t);

        if (k != k_cur) {   // <=2x per CTA (contiguous chunks)
            k_cur = k;
            const float* Wk = weight + (size_t)k * C_IN * C_OUT;
#pragma unroll
            for (int kt = 0; kt < 8; ++kt)
#pragma unroll
                for (int nt = 0; nt < 4; ++nt) {
                    B[kt][nt][0] = cvt_tf32(Wk[(8 * kt + tig)     * C_OUT + 8 * nt + grp]);
                    B[kt][nt][1] = cvt_tf32(Wk[(8 * kt + tig + 4) * C_OUT + 8 * nt + grp]);
                }
        }

        // ---- issue next tile's async fetches (hidden behind MMA+scatter below) ----
        FENCE_ASYNC();
        const int rows1 = (t + 1 < tEnd) ? ROWS_OF(t + 1) : 0;
        const int rows2 = (t + 2 < tEnd) ? ROWS_OF(t + 2) : 0;
        uint32_t bytes = (uint32_t)(rows1 * (256 + idxsz) + rows2 * idxsz);
        if (bytes && tid == 0) expect_tx(MBAR(cur), bytes);
        if (rows1) {
            if (tid < rows1) {
                long long ii = is64 ? ((const long long*)(smem + OFF_IN(nxt)))[tid]
                                    : (long long)((const int*)(smem + OFF_IN(nxt)))[tid];
                bulk_g2s(sb + OFF_A(nxt) + tid * A_ROW_BYTES, feats + ii * C_IN, 256, MBAR(cur));
            }
            if (tid == 0)
                bulk_g2s(sb + OFF_OUT(nxt), (const char*)out_map + MAP_OFF(t + 1) * idxsz,
                         rows1 * idxsz, MBAR(cur));
        }
        if (rows2 && tid == 1)
            bulk_g2s(sb + OFF_IN(cur), (const char*)in_map + MAP_OFF(t + 2) * idxsz,
                     rows2 * idxsz, MBAR(cur));

        // ---- MMA: 32 rows x 32 cols x 64 k per warp ----
        float acc[2][4][4];
#pragma unroll
        for (int mt = 0; mt < 2; ++mt)
#pragma unroll
            for (int nt = 0; nt < 4; ++nt)
#pragma unroll
                for (int i = 0; i < 4; ++i) acc[mt][nt][i] = 0.f;

        const float* A = (const float*)(smem + OFF_A(cur));
#pragma unroll
        for (int kt = 0; kt < 8; ++kt) {
#pragma unroll
            for (int mt = 0; mt < 2; ++mt) {
                const float* Ar = &A[(wbase + mt * 16 + grp) * A_STRIDE_F + kt * 8 + tig];
                uint32_t a0 = __float_as_uint(Ar[0]);
                uint32_t a1 = __float_as_uint(Ar[8 * A_STRIDE_F]);
                uint32_t a2 = __float_as_uint(Ar[4]);
                uint32_t a3 = __float_as_uint(Ar[8 * A_STRIDE_F + 4]);
#pragma unroll
                for (int nt = 0; nt < 4; ++nt)
                    mma_tf32(acc[mt][nt][0], acc[mt][nt][1], acc[mt][nt][2], acc[mt][nt][3],
                             a0, a1, a2, a3, B[kt][nt][0], B[kt][nt][1]);
            }
        }

        // ---- scatter epilogue ----
        const char* osm = smem + OFF_OUT(cur);
#pragma unroll
        for (int mt = 0; mt < 2; ++mt) {
            int r0 = wbase + mt * 16 + grp;
            int r1 = r0 + 8;
            bool v0 = r0 < rows, v1 = r1 < rows;
            long long o0 = 0, o1 = 0;
            if (v0) o0 = is64 ? ((const long long*)osm)[r0] : (long long)((const int*)osm)[r0];
            if (v1) o1 = is64 ? ((const long long*)osm)[r1] : (long long)((const int*)osm)[r1];
            float* p0 = out + o0 * C_OUT + 2 * tig;
            float* p1 = out + o1 * C_OUT + 2 * tig;
#pragma unroll
            for (int nt = 0; nt < 4; ++nt) {
                if (v0) red_v2(p0 + 8 * nt, acc[mt][nt][0], acc[mt][nt][1]);
                if (v1) red_v2(p1 + 8 * nt, acc[mt][nt][2], acc[mt][nt][3]);
            }
        }
    }
#undef MBAR
#undef ROWS_OF
#undef MAP_OFF
}

extern "C" void kernel_launch(void* const* d_in, const int* in_sizes, int n_in,
                              void* d_out, int out_size) {
    const float* feats  = (const float*)d_in[0];
    const float* weight = (const float*)d_in[1];
    const void*  in_map  = d_in[2];
    const void*  out_map = d_in[3];

    int K = in_sizes[1] / (C_IN * C_OUT);           // 27
    int M = in_sizes[2] / K;                        // 100000
    int tilesPerK = (M + M_TILE - 1) / M_TILE;      // 782
    int nTiles = K * tilesPerK;                     // 21114
    int chunk = (nTiles + GRID - 1) / GRID;         // 48

    static int attr_done = 0;
    if (!attr_done) {
        cudaFuncSetAttribute(spconv_mma,
                             cudaFuncAttributeMaxDynamicSharedMemorySize, SMEM_TOTAL);
        attr_done = 1;
    }

    cudaMemsetAsync(d_out, 0, (size_t)out_size * sizeof(float));
    detect_idx_kernel<<<1, 1>>>((const long long*)in_map);
    spconv_mma<<<GRID, THREADS, SMEM_TOTAL>>>(feats, weight, in_map, out_map,
                                              (float*)d_out, M, tilesPerK, nTiles, chunk);
}